// round 14
// baseline (speedup 1.0000x reference)
#include <cuda_runtime.h>
#include <cuda_bf16.h>
#include <math.h>
#include <stdint.h>

#define Bv 4
#define Nv 2048
#define Fv 256
#define Dv 128
#define Hv 4

// Scratch (device globals per harness rules)
__device__ float g_Xs  [Bv*Nv*Dv];             // X@W_skip + b_skip (f32)
__device__ float g_Hout[Bv*Nv*Dv];             // relu(mean_h heads) (f32)
__device__ __nv_bfloat16 g_Hx0T[Bv*Dv*Nv];     // (X@kernel+bias)^T bf16 [b][d][n]
__device__ __nv_bfloat16 g_Hxb [Bv*Nv*Dv];     // Hx bf16 [b][n][d]
__device__ __nv_bfloat16 g_HxT [Bv*Dv*Nv];     // Hx bf16 [b][d][n]
__device__ __nv_bfloat16 g_Qb  [Hv*Bv*Nv*Dv];  // Q  bf16 [h][b][n][d]
__device__ __nv_bfloat16 g_attnT[Hv*Dv*Dv];    // attn^T bf16 [h][e][d]
__device__ __nv_bfloat16 g_WuT [Dv*Dv];        // Wu^T bf16 [c][k]
__device__ __nv_bfloat16 g_WxT [Dv*Dv];        // Wx^T bf16 [c][k]

// ---------------------------------------------------------------------------
// helpers
// ---------------------------------------------------------------------------
__device__ __forceinline__ float tanh_fast(float x) {
    float y; asm("tanh.approx.f32 %0, %1;" : "=f"(y) : "f"(x)); return y;
}
__device__ __forceinline__ unsigned pack_bf16(float lo, float hi) {
    unsigned d; asm("cvt.rn.bf16x2.f32 %0, %1, %2;" : "=r"(d) : "f"(hi), "f"(lo)); return d;
}
__device__ __forceinline__ unsigned f2tf(float f) {
    unsigned u; asm("cvt.rna.tf32.f32 %0, %1;" : "=r"(u) : "f"(f)); return u;
}
__device__ __forceinline__ void mma_bf16(float c[4], const unsigned a[4], const unsigned b[2]) {
    asm volatile(
        "mma.sync.aligned.m16n8k16.row.col.f32.bf16.bf16.f32 "
        "{%0,%1,%2,%3}, {%4,%5,%6,%7}, {%8,%9}, {%0,%1,%2,%3};"
        : "+f"(c[0]), "+f"(c[1]), "+f"(c[2]), "+f"(c[3])
        : "r"(a[0]), "r"(a[1]), "r"(a[2]), "r"(a[3]), "r"(b[0]), "r"(b[1]));
}
__device__ __forceinline__ void mma_tf32(float c[4], const unsigned a[4], const unsigned b[2]) {
    asm volatile(
        "mma.sync.aligned.m16n8k8.row.col.f32.tf32.tf32.f32 "
        "{%0,%1,%2,%3}, {%4,%5,%6,%7}, {%8,%9}, {%0,%1,%2,%3};"
        : "+f"(c[0]), "+f"(c[1]), "+f"(c[2]), "+f"(c[3])
        : "r"(a[0]), "r"(a[1]), "r"(a[2]), "r"(a[3]), "r"(b[0]), "r"(b[1]));
}
__device__ __forceinline__ void ldsm4(unsigned d[4], const unsigned* p) {
    unsigned addr = (unsigned)__cvta_generic_to_shared(p);
    asm volatile("ldmatrix.sync.aligned.m8n8.x4.shared.b16 {%0,%1,%2,%3}, [%4];"
        : "=r"(d[0]), "=r"(d[1]), "=r"(d[2]), "=r"(d[3]) : "r"(addr));
}
__device__ __forceinline__ void cpa16(unsigned* dst, const void* src) {
    unsigned d = (unsigned)__cvta_generic_to_shared(dst);
    asm volatile("cp.async.cg.shared.global [%0], [%1], 16;" :: "r"(d), "l"(src));
}
__device__ __forceinline__ unsigned ldsu(const float* p) { return __float_as_uint(*p); }

// A-fragment (16 rows x 16k) lane offset within array of word-stride S
#define AOFF(S) (((lane) & 15) * (S) + (((lane) >> 4) << 2))
// B two-octet (16 n-rows x 16k) lane offset
#define BOFF(S) ((((lane) & 7) + (((lane) >> 4) << 3)) * (S) + ((((lane) >> 3) & 1) << 2))

// strides (== 4 or 12 mod 32 -> conflict-free)
#define WQ 68    // 64 k-words + 4 pad (bf16)
#define WT 36    // 32 k-words + 4 pad (bf16)
#define WG 132   // 128 k-words + 4 pad (bf16, gate K=256)
#define SB 140   // tf32 B stride (mod 32 == 12)
#define SA 68    // tf32 A stride (mod 32 == 4)

// attn kernel smem plan (words): sQ | buf0 | buf1 (double buffer)
#define TILE_W (64*WQ + 128*WT + 64*68)   // sHx + sHxT + sAr = 13312
#define SQ_W   (4*64*WQ)                  // 17408
#define NT     (Nv/64)                    // 32 m-tiles

// aggr kernel double-buffer chunk (words): sA [64][36] + sB [128][36]
#define AG_W (64*36 + 128*36)             // 6912

// ---------------------------------------------------------------------------
// K0: prep — attnT, WuT, WxT (bf16 packed transposes)
// ---------------------------------------------------------------------------
__global__ __launch_bounds__(256) void prep_kernel(
    const float* __restrict__ attn, const float* __restrict__ Wu,
    const float* __restrict__ Wx)
{
    int idx = blockIdx.x * 256 + threadIdx.x;   // 49152 words total
    if (idx < 32768) {                          // attnT: [h][e][dw]
        int h = idx >> 13, e = (idx >> 6) & 127, dw = idx & 63;
        const float* src = attn + (size_t)h * Dv * Dv;
        ((unsigned*)g_attnT)[idx] =
            pack_bf16(src[(2*dw) * Dv + e], src[(2*dw + 1) * Dv + e]);
    } else if (idx < 40960) {                   // WuT: [c][kw]
        int j = idx - 32768; int c = j >> 6, w = j & 63;
        ((unsigned*)g_WuT)[j] = pack_bf16(Wu[(2*w)*Dv + c], Wu[(2*w + 1)*Dv + c]);
    } else {                                    // WxT: [c][kw]
        int j = idx - 40960; int c = j >> 6, w = j & 63;
        ((unsigned*)g_WxT)[j] = pack_bf16(Wx[(2*w)*Dv + c], Wx[(2*w + 1)*Dv + c]);
    }
}

// ---------------------------------------------------------------------------
// K1: proj (tf32 mma): Hx0T = bf16(X@kernel+bias)^T ; Xs = X@W_skip+b_skip (f32)
// ---------------------------------------------------------------------------
__global__ __launch_bounds__(256, 1) void proj_mma_kernel(
    const float* __restrict__ X, const float* __restrict__ Wk,
    const float* __restrict__ bias, const float* __restrict__ Ws,
    const float* __restrict__ bskip)
{
    extern __shared__ float sm[];
    float* sX = sm;             // [64][SA]  X chunk (tf32 bits)
    float* sK = sX + 64*SA;     // [64][SB]  kernel chunk (tf32)
    float* sW = sK + 64*SB;     // [64][SB]  W_skip chunk (tf32)
    const int tid = threadIdx.x, warp = tid >> 5, lane = tid & 31;
    const int wn = warp >> 1, wd = warp & 1;
    const int lr = lane >> 2, lc = lane & 3;
    const int row0 = blockIdx.x * 64;

    float accK[8][4], accW[8][4];
#pragma unroll
    for (int j = 0; j < 8; j++)
#pragma unroll
        for (int i = 0; i < 4; i++) { accK[j][i] = 0.f; accW[j][i] = 0.f; }

    for (int kt = 0; kt < Fv/64; kt++) {
        const int k0 = kt * 64;
#pragma unroll
        for (int s = 0; s < 4; s++) {      // X tile 64x64
            int i4 = tid + 256*s; int r = i4 >> 4, c4 = (i4 & 15)*4;
            float4 v = *(const float4*)&X[(size_t)(row0 + r)*Fv + k0 + c4];
            unsigned* d = (unsigned*)&sX[r*SA + c4];
            d[0]=f2tf(v.x); d[1]=f2tf(v.y); d[2]=f2tf(v.z); d[3]=f2tf(v.w);
        }
#pragma unroll
        for (int s = 0; s < 8; s++) {      // Wk/Ws chunks 64x128
            int i4 = tid + 256*s; int r = i4 >> 5, c4 = (i4 & 31)*4;
            float4 v1 = *(const float4*)&Wk[(size_t)(k0 + r)*Dv + c4];
            float4 v2 = *(const float4*)&Ws[(size_t)(k0 + r)*Dv + c4];
            unsigned* d1 = (unsigned*)&sK[r*SB + c4];
            unsigned* d2 = (unsigned*)&sW[r*SB + c4];
            d1[0]=f2tf(v1.x); d1[1]=f2tf(v1.y); d1[2]=f2tf(v1.z); d1[3]=f2tf(v1.w);
            d2[0]=f2tf(v2.x); d2[1]=f2tf(v2.y); d2[2]=f2tf(v2.z); d2[3]=f2tf(v2.w);
        }
        __syncthreads();
#pragma unroll
        for (int ks = 0; ks < 8; ks++) {
            unsigned a[4];
            const float* aw = sX + (16*wn)*SA;
            a[0] = ldsu(&aw[ lr    *SA + 8*ks + lc    ]);
            a[1] = ldsu(&aw[(lr+8) *SA + 8*ks + lc    ]);
            a[2] = ldsu(&aw[ lr    *SA + 8*ks + lc + 4]);
            a[3] = ldsu(&aw[(lr+8) *SA + 8*ks + lc + 4]);
#pragma unroll
            for (int j = 0; j < 8; j++) {
                unsigned b1[2], b2[2];
                b1[0] = ldsu(&sK[(8*ks + lc    )*SB + 64*wd + 8*j + lr]);
                b1[1] = ldsu(&sK[(8*ks + lc + 4)*SB + 64*wd + 8*j + lr]);
                b2[0] = ldsu(&sW[(8*ks + lc    )*SB + 64*wd + 8*j + lr]);
                b2[1] = ldsu(&sW[(8*ks + lc + 4)*SB + 64*wd + 8*j + lr]);
                mma_tf32(accK[j], a, b1);
                mma_tf32(accW[j], a, b2);
            }
        }
        __syncthreads();
    }
#pragma unroll
    for (int j = 0; j < 8; j++) {
        int rr = row0 + 16*wn + lr, cc = 64*wd + 8*j + 2*lc;
        int b0_ = rr >> 11, n0_ = rr & (Nv - 1);
        int b1_ = (rr+8) >> 11, n1_ = (rr+8) & (Nv - 1);
        *(float2*)&g_Xs[(size_t)rr    *Dv + cc] =
            make_float2(accW[j][0] + bskip[cc], accW[j][1] + bskip[cc+1]);
        *(float2*)&g_Xs[(size_t)(rr+8)*Dv + cc] =
            make_float2(accW[j][2] + bskip[cc], accW[j][3] + bskip[cc+1]);
        g_Hx0T[((size_t)b0_*Dv + cc  )*Nv + n0_] = __float2bfloat16(accK[j][0] + bias[cc]);
        g_Hx0T[((size_t)b0_*Dv + cc+1)*Nv + n0_] = __float2bfloat16(accK[j][1] + bias[cc+1]);
        g_Hx0T[((size_t)b1_*Dv + cc  )*Nv + n1_] = __float2bfloat16(accK[j][2] + bias[cc]);
        g_Hx0T[((size_t)b1_*Dv + cc+1)*Nv + n1_] = __float2bfloat16(accK[j][3] + bias[cc+1]);
    }
}

// ---------------------------------------------------------------------------
// K2: Hx = A @ Hx0  (bf16 mma + ldmatrix), double-buffered pipeline (R13).
// ---------------------------------------------------------------------------
__global__ __launch_bounds__(256, 1) void aggr_bf16_kernel(
    const float* __restrict__ A, float* __restrict__ outA)
{
    extern __shared__ unsigned smw[];
    const int tid = threadIdx.x, warp = tid >> 5, lane = tid & 31;
    const int lr = lane >> 2, lc = lane & 3;
    const int an = warp & 1, ad = (warp >> 1) & 1, ak = warp >> 2;
    const int b = blockIdx.y, n0 = blockIdx.x * 64;
    const float* Ab = A + (size_t)b * Nv * Nv;
    const unsigned* HtW0 = (const unsigned*)g_Hx0T + (size_t)b * Dv * (Nv/2);
    const int aoff = AOFF(36), boff = BOFF(36);
    const int rA = tid >> 5, wA = tid & 31;

    float2 aReg[8];
    auto load_a = [&](int k0) {
#pragma unroll
        for (int s = 0; s < 8; s++)
            aReg[s] = *(const float2*)&Ab[(size_t)(n0 + rA + 8*s)*Nv + k0 + 2*wA];
    };
    auto store_a = [&](unsigned* sA, int k0) {
#pragma unroll
        for (int s = 0; s < 8; s++) {
            sA[(rA + 8*s)*36 + wA] = pack_bf16(aReg[s].x, aReg[s].y);
            *(float2*)&outA[((size_t)b*Nv + n0 + rA + 8*s)*Nv + k0 + 2*wA] = aReg[s];
        }
    };
    auto issue_b = [&](unsigned* sB, int k0) {
#pragma unroll
        for (int s = 0; s < 4; s++) {
            int i4 = tid + 256*s; int d = i4 >> 3, c4 = (i4 & 7) << 2;
            cpa16(&sB[d*36 + c4], &HtW0[(size_t)d*(Nv/2) + (k0 >> 1) + c4]);
        }
    };

    float acc[2][8][4];
#pragma unroll
    for (int f = 0; f < 2; f++)
#pragma unroll
        for (int j = 0; j < 8; j++)
#pragma unroll
            for (int i = 0; i < 4; i++) acc[f][j][i] = 0.f;

    load_a(0);
    issue_b(smw + 64*36, 0);
    asm volatile("cp.async.commit_group;");

    for (int kt = 0; kt < Nv/64; kt++) {
        const int k0 = kt * 64;
        unsigned* cur = smw + (kt & 1) * AG_W;
        unsigned* sA = cur;
        unsigned* sB = cur + 64*36;

        store_a(sA, k0);
        if (kt + 1 < Nv/64) {
            issue_b(smw + ((kt + 1) & 1) * AG_W + 64*36, k0 + 64);
            asm volatile("cp.async.commit_group;");
            asm volatile("cp.async.wait_group 1;");
        } else {
            asm volatile("cp.async.wait_group 0;");
        }
        __syncthreads();

        if (kt + 1 < Nv/64) load_a(k0 + 64);

#pragma unroll
        for (int ks = 0; ks < 2; ks++) {
            int kw = ak*16 + ks*8;
            unsigned a0[4], a1[4], bb[4];
            ldsm4(a0, sA + (an*32     )*36 + aoff + kw);
            ldsm4(a1, sA + (an*32 + 16)*36 + aoff + kw);
#pragma unroll
            for (int p = 0; p < 4; p++) {
                ldsm4(bb, sB + (ad*64 + p*16)*36 + boff + kw);
                mma_bf16(acc[0][2*p    ], a0, bb    );
                mma_bf16(acc[0][2*p + 1], a0, bb + 2);
                mma_bf16(acc[1][2*p    ], a1, bb    );
                mma_bf16(acc[1][2*p + 1], a1, bb + 2);
            }
        }
        __syncthreads();
    }
    float* red = (float*)smw;
    if (ak == 1) {
        int base = (((warp - 4) * 32) + lane) * 64;
#pragma unroll
        for (int f = 0; f < 2; f++)
#pragma unroll
            for (int j = 0; j < 8; j++)
#pragma unroll
                for (int i = 0; i < 4; i++)
                    red[base + f*32 + j*4 + i] = acc[f][j][i];
    }
    __syncthreads();
    if (ak == 0) {
        int base = ((warp * 32) + lane) * 64;
        unsigned* Pb = (unsigned*)g_Hxb;
        __nv_bfloat16* Tb = g_HxT + (size_t)b * Dv * Nv;
#pragma unroll
        for (int f = 0; f < 2; f++)
#pragma unroll
            for (int j = 0; j < 8; j++) {
                float v0 = acc[f][j][0] + red[base + f*32 + j*4 + 0];
                float v1 = acc[f][j][1] + red[base + f*32 + j*4 + 1];
                float v2 = acc[f][j][2] + red[base + f*32 + j*4 + 2];
                float v3 = acc[f][j][3] + red[base + f*32 + j*4 + 3];
                int n  = an*32 + f*16 + lr;
                int cc = ad*64 + j*8 + 2*lc;
                Pb[(((size_t)b*Nv + n0+n  )*Dv + cc) >> 1] = pack_bf16(v0, v1);
                Pb[(((size_t)b*Nv + n0+n+8)*Dv + cc) >> 1] = pack_bf16(v2, v3);
                Tb[(size_t)(cc  )*Nv + n0+n  ] = __float2bfloat16(v0);
                Tb[(size_t)(cc+1)*Nv + n0+n  ] = __float2bfloat16(v1);
                Tb[(size_t)(cc  )*Nv + n0+n+8] = __float2bfloat16(v2);
                Tb[(size_t)(cc+1)*Nv + n0+n+8] = __float2bfloat16(v3);
            }
    }
}

// ---------------------------------------------------------------------------
// K3: Q[h,b] = Hx[b] @ attn[h]  (bf16 mma + ldmatrix). grid(32,B,H).
// ---------------------------------------------------------------------------
__global__ __launch_bounds__(256, 1) void q_bf16_kernel()
{
    extern __shared__ unsigned smw[];
    unsigned* sHx = smw;            // [64][WQ]
    unsigned* sAt = smw + 64*WQ;    // [128][WQ]
    const int tid = threadIdx.x, warp = tid >> 5, lane = tid & 31;
    const int lr = lane >> 2, lc = lane & 3;
    const int qn = warp & 1, qd = warp >> 1;
    const int b = blockIdx.y, h = blockIdx.z, n0 = blockIdx.x * 64;
    const unsigned* HbW = (const unsigned*)g_Hxb + (size_t)b * Nv * (Dv/2);
    const unsigned* ATW = (const unsigned*)g_attnT + (size_t)h * Dv * (Dv/2);
    const int aoff = AOFF(WQ), boff = BOFF(WQ);

#pragma unroll
    for (int s = 0; s < 4; s++) {
        int i4 = tid + 256*s; int r = i4 >> 4, c4 = (i4 & 15) << 2;
        *(uint4*)&sHx[r*WQ + c4] = *(const uint4*)&HbW[(size_t)(n0 + r)*(Dv/2) + c4];
    }
#pragma unroll
    for (int s = 0; s < 8; s++) {
        int i4 = tid + 256*s; int e = i4 >> 4, c4 = (i4 & 15) << 2;
        *(uint4*)&sAt[e*WQ + c4] = *(const uint4*)&ATW[(size_t)e*(Dv/2) + c4];
    }
    __syncthreads();

    float acc[2][4][4];
#pragma unroll
    for (int f = 0; f < 2; f++)
#pragma unroll
        for (int j = 0; j < 4; j++)
#pragma unroll
            for (int i = 0; i < 4; i++) acc[f][j][i] = 0.f;

#pragma unroll
    for (int ks = 0; ks < 8; ks++) {
        unsigned a0[4], a1[4], bb[4];
        ldsm4(a0, sHx + (qn*32     )*WQ + aoff + 8*ks);
        ldsm4(a1, sHx + (qn*32 + 16)*WQ + aoff + 8*ks);
#pragma unroll
        for (int p = 0; p < 2; p++) {
            ldsm4(bb, sAt + (qd*32 + p*16)*WQ + boff + 8*ks);
            mma_bf16(acc[0][2*p    ], a0, bb    );
            mma_bf16(acc[0][2*p + 1], a0, bb + 2);
            mma_bf16(acc[1][2*p    ], a1, bb    );
            mma_bf16(acc[1][2*p + 1], a1, bb + 2);
        }
    }
    unsigned* Ob = (unsigned*)g_Qb;
#pragma unroll
    for (int f = 0; f < 2; f++)
#pragma unroll
        for (int j = 0; j < 4; j++) {
            int n = qn*32 + f*16 + lr, cc = qd*32 + j*8 + 2*lc;
            Ob[((((size_t)h*Bv + b)*Nv + n0+n  )*Dv + cc) >> 1] =
                pack_bf16(acc[f][j][0], acc[f][j][1]);
            Ob[((((size_t)h*Bv + b)*Nv + n0+n+8)*Dv + cc) >> 1] =
                pack_bf16(acc[f][j][2], acc[f][j][3]);
        }
}

// ---------------------------------------------------------------------------
// K4: fused attention, 512 threads / 16 warps (4 g1n x 4 g1m).
// GEMM1 warp tile 16n x 16m per head (C in f32 regs, register-direct to
// GEMM2 A-frag); GEMM2 acc 16n x 128d over the warp's 16m; reduce over the
// 4 g1m warps. Double-buffered cp.async tiles, 2 syncs per m-tile.
// ---------------------------------------------------------------------------
__global__ __launch_bounds__(512, 1) void attn_bf16_kernel(const float* __restrict__ A)
{
    extern __shared__ unsigned smw[];
    unsigned* sQ = smw;                 // [4][64][WQ]

    const int tid = threadIdx.x, warp = tid >> 5, lane = tid & 31;
    const int lr = lane >> 2, lc = lane & 3;
    const int g1n = warp & 3, g1m = warp >> 2;   // 4 x 4
    const int b = blockIdx.y, n0 = blockIdx.x * 64;
    const float* Ab = A + (size_t)b * Nv * Nv;
    const unsigned* HbW = (const unsigned*)g_Hxb + (size_t)b * Nv * (Dv/2);
    const unsigned* HtW = (const unsigned*)g_HxT + (size_t)b * Dv * (Nv/2);
    const int aoffQ = AOFF(WQ), boffQ = BOFF(WQ), boffT = BOFF(WT);

    // tile issue: 6 cp.async per thread at 512 threads
    auto issue_tile = [&](unsigned* buf, int m0) {
        unsigned* dHx  = buf;
        unsigned* dHxT = buf + 64*WQ;
        float*    dAr  = (float*)(buf + 64*WQ + 128*WT);
#pragma unroll
        for (int s = 0; s < 2; s++) {
            int i4 = tid + 512*s; int r = i4 >> 4, c4 = (i4 & 15) << 2;
            cpa16(&dHx[r*WQ + c4], &HbW[(size_t)(m0 + r)*(Dv/2) + c4]);
        }
#pragma unroll
        for (int s = 0; s < 2; s++) {
            int i4 = tid + 512*s; int d = i4 >> 3, c4 = (i4 & 7) << 2;
            cpa16(&dHxT[d*WT + c4], &HtW[(size_t)d*(Nv/2) + (m0 >> 1) + c4]);
        }
#pragma unroll
        for (int s = 0; s < 2; s++) {
            int i4 = tid + 512*s; int r = i4 >> 4, c4 = (i4 & 15) << 2;
            cpa16((unsigned*)&dAr[r*68 + c4], &Ab[(size_t)(n0 + r)*Nv + m0 + c4]);
        }
    };

    issue_tile(sQ + SQ_W, 0);
    asm volatile("cp.async.commit_group;");

    // load Q (all 4 heads): 4096 uint4, 8 per thread
#pragma unroll
    for (int s = 0; s < 8; s++) {
        int i4 = tid + 512*s;
        int h = i4 >> 10, r = (i4 >> 4) & 63, c4 = (i4 & 15) * 4;
        const uint4* src = (const uint4*)((const unsigned*)g_Qb +
            (((size_t)h*Bv + b)*Nv + n0 + r) * (Dv/2));
        *(uint4*)&sQ[(h*64 + r)*WQ + c4] = src[c4 >> 2];
    }

    float acc[16][4];
#pragma unroll
    for (int j = 0; j < 16; j++)
#pragma unroll
        for (int i = 0; i < 4; i++) acc[j][i] = 0.f;

    for (int mt = 0; mt < NT; mt++) {
        unsigned* cur = sQ + SQ_W + (mt & 1) * TILE_W;
        if (mt + 1 < NT) {
            issue_tile(sQ + SQ_W + ((mt + 1) & 1) * TILE_W, (mt + 1) * 64);
            asm volatile("cp.async.commit_group;");
            asm volatile("cp.async.wait_group 1;");
        } else {
            asm volatile("cp.async.wait_group 0;");
        }
        __syncthreads();

        const unsigned* bHx  = cur;
        const unsigned* bHxT = cur + 64*WQ;
        const float*    bAr  = (const float*)(cur + 64*WQ + 128*WT);

        // hoist this warp's A values (16n x 16m)
        float aA[2][4];
#pragma unroll
        for (int jm = 0; jm < 2; jm++) {
            int n  = g1n*16 + lr;
            int mm = g1m*16 + jm*8 + 2*lc;
            float2 a01 = *(const float2*)&bAr[ n    *68 + mm];
            float2 a23 = *(const float2*)&bAr[(n+8) *68 + mm];
            aA[jm][0] = a01.x; aA[jm][1] = a01.y;
            aA[jm][2] = a23.x; aA[jm][3] = a23.y;
        }

        // C = sum_h tanh(A * S_h)  (16n x 16m per warp)
        float C[2][4];
#pragma unroll
        for (int jm = 0; jm < 2; jm++)
#pragma unroll
            for (int i = 0; i < 4; i++) C[jm][i] = 0.f;

#pragma unroll
        for (int h = 0; h < Hv; h++) {
            float s4[2][4];
#pragma unroll
            for (int jm = 0; jm < 2; jm++)
#pragma unroll
                for (int i = 0; i < 4; i++) s4[jm][i] = 0.f;
            const unsigned* q = sQ + (h*64 + g1n*16)*WQ;
#pragma unroll
            for (int ks = 0; ks < 8; ks++) {
                unsigned a0[4], bb[4];
                ldsm4(a0, q + aoffQ + 8*ks);
                ldsm4(bb, bHx + (g1m*16)*WQ + boffQ + 8*ks);
                mma_bf16(s4[0], a0, bb    );
                mma_bf16(s4[1], a0, bb + 2);
            }
#pragma unroll
            for (int jm = 0; jm < 2; jm++)
#pragma unroll
                for (int i = 0; i < 4; i++)
                    C[jm][i] += tanh_fast(aA[jm][i] * s4[jm][i]);
        }

        // C-fragment IS the GEMM2 A-fragment (k = this warp's 16m)
        unsigned aC[4];
        aC[0] = pack_bf16(C[0][0], C[0][1]);
        aC[1] = pack_bf16(C[0][2], C[0][3]);
        aC[2] = pack_bf16(C[1][0], C[1][1]);
        aC[3] = pack_bf16(C[1][2], C[1][3]);

        // GEMM2: acc(16n x 128d, partial over this warp's 16m)
#pragma unroll
        for (int p = 0; p < 8; p++) {
            unsigned bb[4];
            ldsm4(bb, bHxT + (p*16)*WT + boffT + g1m*8);
            mma_bf16(acc[2*p    ], aC, bb    );
            mma_bf16(acc[2*p + 1], aC, bb + 2);
        }
        __syncthreads();
    }

    // ---- reduce over the 4 g1m warps (per g1n), then Hout
    float* red = (float*)smw;    // 12 warps x 32 lanes x 64 floats = 24576 words
    if (g1m > 0) {
        int base = ((((g1m - 1)*4 + g1n) * 32) + lane) * 64;
#pragma unroll
        for (int j = 0; j < 16; j++)
#pragma unroll
            for (int i = 0; i < 4; i++)
                red[base + j*4 + i] = acc[j][i];
    }
    __syncthreads();
    if (g1m == 0) {
        float* Ho = g_Hout + ((size_t)b*Nv + n0)*Dv;
#pragma unroll
        for (int w = 0; w < 3; w++) {
            int base = (((w*4 + g1n) * 32) + lane) * 64;
#pragma unroll
            for (int j = 0; j < 16; j++)
#pragma unroll
                for (int i = 0; i < 4; i++)
                    acc[j][i] += red[base + j*4 + i];
        }
#pragma unroll
        for (int j = 0; j < 16; j++) {
            int n = g1n*16 + lr;
            int d = (j >> 1)*16 + (j & 1)*8 + 2*lc;
            float v0 = fmaxf(acc[j][0] * 0.25f, 0.f);
            float v1 = fmaxf(acc[j][1] * 0.25f, 0.f);
            float v2 = fmaxf(acc[j][2] * 0.25f, 0.f);
            float v3 = fmaxf(acc[j][3] * 0.25f, 0.f);
            *(float2*)&Ho[(size_t)n    *Dv + d] = make_float2(v0, v1);
            *(float2*)&Ho[(size_t)(n+8)*Dv + d] = make_float2(v2, v3);
        }
    }
}

// ---------------------------------------------------------------------------
// K5: gate (bf16 mma, K=256 fused): z = sigmoid([Hout|Xs]@[WuT;WxT] + biases)
//     out = Hout*z + Xs*(1-z)   (blend in f32)
// ---------------------------------------------------------------------------
__global__ __launch_bounds__(256, 1) void gate_mma_kernel(
    const float* __restrict__ bu, const float* __restrict__ bx,
    const float* __restrict__ ub, float* __restrict__ out)
{
    extern __shared__ unsigned smw[];
    float*    sHo = (float*)smw;            // [64][132] f32
    float*    sXs = sHo + 64*132;           // [64][132] f32
    unsigned* sAg = smw + 2*64*132;         // [64][WG]
    unsigned* sBg = sAg + 64*WG;            // [128][WG]
    const int tid = threadIdx.x, warp = tid >> 5, lane = tid & 31;
    const int lr = lane >> 2, lc = lane & 3;
    const int gn = warp & 1, gc = warp >> 1;
    const int row0 = blockIdx.x * 64;
    const int aoff = AOFF(WG), boff = BOFF(WG);

#pragma unroll
    for (int s = 0; s < 8; s++) {
        int i4 = tid + 256*s; int r = i4 >> 5, c4 = (i4 & 31) * 4;
        float4 vh = *(const float4*)&g_Hout[(size_t)(row0 + r)*Dv + c4];
        float4 vx = *(const float4*)&g_Xs [(size_t)(row0 + r)*Dv + c4];
        *(float4*)&sHo[r*132 + c4] = vh;
        *(float4*)&sXs[r*132 + c4] = vx;
        sAg[r*WG + (c4 >> 1)    ]      = pack_bf16(vh.x, vh.y);
        sAg[r*WG + (c4 >> 1) + 1]      = pack_bf16(vh.z, vh.w);
        sAg[r*WG + 64 + (c4 >> 1)    ] = pack_bf16(vx.x, vx.y);
        sAg[r*WG + 64 + (c4 >> 1) + 1] = pack_bf16(vx.z, vx.w);
    }
#pragma unroll
    for (int s = 0; s < 8; s++) {
        int i4 = tid + 256*s; int c = i4 >> 4, w4 = (i4 & 15) << 2;
        *(uint4*)&sBg[c*WG + w4]      = *(const uint4*)&((const unsigned*)g_WuT)[(size_t)c*64 + w4];
        *(uint4*)&sBg[c*WG + 64 + w4] = *(const uint4*)&((const unsigned*)g_WxT)[(size_t)c*64 + w4];
    }
    __syncthreads();

    float acc[2][4][4];
#pragma unroll
    for (int f = 0; f < 2; f++)
#pragma unroll
        for (int j = 0; j < 4; j++)
#pragma unroll
            for (int i = 0; i < 4; i++) acc[f][j][i] = 0.f;

#pragma unroll
    for (int ks = 0; ks < 16; ks++) {      // K = 256
        unsigned a0[4], a1[4], bb[4];
        ldsm4(a0, sAg + (gn*32     )*WG + aoff + 8*ks);
        ldsm4(a1, sAg + (gn*32 + 16)*WG + aoff + 8*ks);
#pragma unroll
        for (int p = 0; p < 2; p++) {
            ldsm4(bb, sBg + (gc*32 + p*16)*WG + boff + 8*ks);
            mma_bf16(acc[0][2*p    ], a0, bb    );
            mma_bf16(acc[0][2*p + 1], a0, bb + 2);
            mma_bf16(acc[1][2*p    ], a1, bb    );
            mma_bf16(acc[1][2*p + 1], a1, bb + 2);
        }
    }

#pragma unroll
    for (int f = 0; f < 2; f++)
#pragma unroll
        for (int j = 0; j < 4; j++) {
            int n = gn*32 + f*16 + lr, cc = gc*32 + j*8 + 2*lc;
            float bs0 = bu[cc]   + bx[cc]   + ub[cc];
            float bs1 = bu[cc+1] + bx[cc+1] + ub[cc+1];
            float2 h0 = *(const float2*)&sHo[ n    *132 + cc];
            float2 h1 = *(const float2*)&sHo[(n+8) *132 + cc];
            float2 x0 = *(const float2*)&sXs[ n    *132 + cc];
            float2 x1 = *(const float2*)&sXs[(n+8) *132 + cc];
            float z0 = 1.f / (1.f + expf(-(acc[f][j][0] + bs0)));
            float z1 = 1.f / (1.f + expf(-(acc[f][j][1] + bs1)));
            float z2 = 1.f / (1.f + expf(-(acc[f][j][2] + bs0)));
            float z3 = 1.f / (1.f + expf(-(acc[f][j][3] + bs1)));
            *(float2*)&out[(size_t)(row0 + n    )*Dv + cc] =
                make_float2(h0.x*z0 + x0.x*(1.f - z0), h0.y*z1 + x0.y*(1.f - z1));
            *(float2*)&out[(size_t)(row0 + n + 8)*Dv + cc] =
                make_float2(h1.x*z2 + x1.x*(1.f - z2), h1.y*z3 + x1.y*(1.f - z3));
        }
}

// ---------------------------------------------------------------------------
extern "C" void kernel_launch(void* const* d_in, const int* in_sizes, int n_in,
                              void* d_out, int out_size)
{
    const float* X      = (const float*)d_in[0];
    const float* A      = (const float*)d_in[1];
    const float* Wk     = (const float*)d_in[2];
    const float* bias   = (const float*)d_in[3];
    const float* ub     = (const float*)d_in[4];
    const float* attn   = (const float*)d_in[5];
    const float* Wskip  = (const float*)d_in[6];
    const float* bskip  = (const float*)d_in[7];
    const float* Wu     = (const float*)d_in[8];
    const float* bu     = (const float*)d_in[9];
    const float* Wx     = (const float*)d_in[10];
    const float* bx     = (const float*)d_in[11];
    float* out = (float*)d_out;

    const int SM1 = (64*SA + 2*64*SB) * 4;
    const int SM2 = (2*AG_W) * 4;
    const int SM3 = (64*WQ + 128*WQ) * 4;
    const int SM4 = (SQ_W + 2*TILE_W) * 4;          // 176,128 B
    const int SM5 = (2*64*132 + 64*WG + 128*WG) * 4;
    cudaFuncSetAttribute(proj_mma_kernel,  cudaFuncAttributeMaxDynamicSharedMemorySize, SM1);
    cudaFuncSetAttribute(aggr_bf16_kernel, cudaFuncAttributeMaxDynamicSharedMemorySize, SM2);
    cudaFuncSetAttribute(q_bf16_kernel,    cudaFuncAttributeMaxDynamicSharedMemorySize, SM3);
    cudaFuncSetAttribute(attn_bf16_kernel, cudaFuncAttributeMaxDynamicSharedMemorySize, SM4);
    cudaFuncSetAttribute(gate_mma_kernel,  cudaFuncAttributeMaxDynamicSharedMemorySize, SM5);

    prep_kernel     <<<192, 256>>>(attn, Wu, Wx);
    proj_mma_kernel <<<(Bv*Nv)/64, 256, SM1>>>(X, Wk, bias, Wskip, bskip);
    aggr_bf16_kernel<<<dim3(Nv/64, Bv),     256, SM2>>>(A, out + (size_t)Bv*Nv*Dv);
    q_bf16_kernel   <<<dim3(Nv/64, Bv, Hv), 256, SM3>>>();
    attn_bf16_kernel<<<dim3(Nv/64, Bv),     512, SM4>>>(A);
    gate_mma_kernel <<<(Bv*Nv)/64, 256, SM5>>>(bu, bx, ub, out);
}

// round 15
// speedup vs baseline: 1.1034x; 1.1034x over previous
#include <cuda_runtime.h>
#include <cuda_bf16.h>
#include <math.h>
#include <stdint.h>

#define Bv 4
#define Nv 2048
#define Fv 256
#define Dv 128
#define Hv 4

// Scratch (device globals per harness rules)
__device__ float g_Xs  [Bv*Nv*Dv];             // X@W_skip + b_skip (f32)
__device__ float g_Hout[Bv*Nv*Dv];             // relu(mean_h heads) (f32)
__device__ __nv_bfloat16 g_Hx0T[Bv*Dv*Nv];     // (X@kernel+bias)^T bf16 [b][d][n]
__device__ __nv_bfloat16 g_Hxb [Bv*Nv*Dv];     // Hx bf16 [b][n][d]
__device__ __nv_bfloat16 g_HxT [Bv*Dv*Nv];     // Hx bf16 [b][d][n]
__device__ __nv_bfloat16 g_attnT[Hv*Dv*Dv];    // attn^T bf16 [h][e][d]
__device__ __nv_bfloat16 g_WuT [Dv*Dv];        // Wu^T bf16 [c][k]
__device__ __nv_bfloat16 g_WxT [Dv*Dv];        // Wx^T bf16 [c][k]

// ---------------------------------------------------------------------------
// helpers
// ---------------------------------------------------------------------------
__device__ __forceinline__ float tanh_fast(float x) {
    float y; asm("tanh.approx.f32 %0, %1;" : "=f"(y) : "f"(x)); return y;
}
__device__ __forceinline__ unsigned pack_bf16(float lo, float hi) {
    unsigned d; asm("cvt.rn.bf16x2.f32 %0, %1, %2;" : "=r"(d) : "f"(hi), "f"(lo)); return d;
}
__device__ __forceinline__ unsigned f2tf(float f) {
    unsigned u; asm("cvt.rna.tf32.f32 %0, %1;" : "=r"(u) : "f"(f)); return u;
}
__device__ __forceinline__ void mma_bf16(float c[4], const unsigned a[4], const unsigned b[2]) {
    asm volatile(
        "mma.sync.aligned.m16n8k16.row.col.f32.bf16.bf16.f32 "
        "{%0,%1,%2,%3}, {%4,%5,%6,%7}, {%8,%9}, {%0,%1,%2,%3};"
        : "+f"(c[0]), "+f"(c[1]), "+f"(c[2]), "+f"(c[3])
        : "r"(a[0]), "r"(a[1]), "r"(a[2]), "r"(a[3]), "r"(b[0]), "r"(b[1]));
}
__device__ __forceinline__ void mma_tf32(float c[4], const unsigned a[4], const unsigned b[2]) {
    asm volatile(
        "mma.sync.aligned.m16n8k8.row.col.f32.tf32.tf32.f32 "
        "{%0,%1,%2,%3}, {%4,%5,%6,%7}, {%8,%9}, {%0,%1,%2,%3};"
        : "+f"(c[0]), "+f"(c[1]), "+f"(c[2]), "+f"(c[3])
        : "r"(a[0]), "r"(a[1]), "r"(a[2]), "r"(a[3]), "r"(b[0]), "r"(b[1]));
}
__device__ __forceinline__ void ldsm4(unsigned d[4], const unsigned* p) {
    unsigned addr = (unsigned)__cvta_generic_to_shared(p);
    asm volatile("ldmatrix.sync.aligned.m8n8.x4.shared.b16 {%0,%1,%2,%3}, [%4];"
        : "=r"(d[0]), "=r"(d[1]), "=r"(d[2]), "=r"(d[3]) : "r"(addr));
}
__device__ __forceinline__ void cpa16(unsigned* dst, const void* src) {
    unsigned d = (unsigned)__cvta_generic_to_shared(dst);
    asm volatile("cp.async.cg.shared.global [%0], [%1], 16;" :: "r"(d), "l"(src));
}
__device__ __forceinline__ unsigned ldsu(const float* p) { return __float_as_uint(*p); }

// A-fragment (16 rows x 16k) lane offset within array of word-stride S
#define AOFF(S) (((lane) & 15) * (S) + (((lane) >> 4) << 2))
// B two-octet (16 n-rows x 16k) lane offset
#define BOFF(S) ((((lane) & 7) + (((lane) >> 4) << 3)) * (S) + ((((lane) >> 3) & 1) << 2))

// strides (== 4 or 12 mod 32 -> conflict-free)
#define WQ 68    // 64 k-words + 4 pad (bf16)
#define WT 36    // 32 k-words + 4 pad (bf16)
#define WG 132   // 128 k-words + 4 pad (bf16, gate K=256)
#define SB 140   // tf32 B stride (mod 32 == 12)
#define SA 68    // tf32 A stride (mod 32 == 4)

// attn kernel smem plan (words): sQ | buf0 | buf1 (double buffer)
#define TILE_W (64*WQ + 128*WT + 64*68)   // sHx + sHxT + sAr = 13312
#define SQ_W   (4*64*WQ)                  // 17408
#define NT     (Nv/64)                    // 32 m-tiles

// aggr kernel double-buffer chunk (words): sA [64][36] + sB [128][36]
#define AG_W (64*36 + 128*36)             // 6912

// ---------------------------------------------------------------------------
// K0: prep — attnT, WuT, WxT (bf16 packed transposes)
// ---------------------------------------------------------------------------
__global__ __launch_bounds__(256) void prep_kernel(
    const float* __restrict__ attn, const float* __restrict__ Wu,
    const float* __restrict__ Wx)
{
    int idx = blockIdx.x * 256 + threadIdx.x;   // 49152 words total
    if (idx < 32768) {                          // attnT: [h][e][dw]
        int h = idx >> 13, e = (idx >> 6) & 127, dw = idx & 63;
        const float* src = attn + (size_t)h * Dv * Dv;
        ((unsigned*)g_attnT)[idx] =
            pack_bf16(src[(2*dw) * Dv + e], src[(2*dw + 1) * Dv + e]);
    } else if (idx < 40960) {                   // WuT: [c][kw]
        int j = idx - 32768; int c = j >> 6, w = j & 63;
        ((unsigned*)g_WuT)[j] = pack_bf16(Wu[(2*w)*Dv + c], Wu[(2*w + 1)*Dv + c]);
    } else {                                    // WxT: [c][kw]
        int j = idx - 40960; int c = j >> 6, w = j & 63;
        ((unsigned*)g_WxT)[j] = pack_bf16(Wx[(2*w)*Dv + c], Wx[(2*w + 1)*Dv + c]);
    }
}

// ---------------------------------------------------------------------------
// K1: proj (tf32 mma): Hx0T = bf16(X@kernel+bias)^T ; Xs = X@W_skip+b_skip (f32)
// ---------------------------------------------------------------------------
__global__ __launch_bounds__(256, 1) void proj_mma_kernel(
    const float* __restrict__ X, const float* __restrict__ Wk,
    const float* __restrict__ bias, const float* __restrict__ Ws,
    const float* __restrict__ bskip)
{
    extern __shared__ float sm[];
    float* sX = sm;             // [64][SA]
    float* sK = sX + 64*SA;     // [64][SB]
    float* sW = sK + 64*SB;     // [64][SB]
    const int tid = threadIdx.x, warp = tid >> 5, lane = tid & 31;
    const int wn = warp >> 1, wd = warp & 1;
    const int lr = lane >> 2, lc = lane & 3;
    const int row0 = blockIdx.x * 64;

    float accK[8][4], accW[8][4];
#pragma unroll
    for (int j = 0; j < 8; j++)
#pragma unroll
        for (int i = 0; i < 4; i++) { accK[j][i] = 0.f; accW[j][i] = 0.f; }

    for (int kt = 0; kt < Fv/64; kt++) {
        const int k0 = kt * 64;
#pragma unroll
        for (int s = 0; s < 4; s++) {
            int i4 = tid + 256*s; int r = i4 >> 4, c4 = (i4 & 15)*4;
            float4 v = *(const float4*)&X[(size_t)(row0 + r)*Fv + k0 + c4];
            unsigned* d = (unsigned*)&sX[r*SA + c4];
            d[0]=f2tf(v.x); d[1]=f2tf(v.y); d[2]=f2tf(v.z); d[3]=f2tf(v.w);
        }
#pragma unroll
        for (int s = 0; s < 8; s++) {
            int i4 = tid + 256*s; int r = i4 >> 5, c4 = (i4 & 31)*4;
            float4 v1 = *(const float4*)&Wk[(size_t)(k0 + r)*Dv + c4];
            float4 v2 = *(const float4*)&Ws[(size_t)(k0 + r)*Dv + c4];
            unsigned* d1 = (unsigned*)&sK[r*SB + c4];
            unsigned* d2 = (unsigned*)&sW[r*SB + c4];
            d1[0]=f2tf(v1.x); d1[1]=f2tf(v1.y); d1[2]=f2tf(v1.z); d1[3]=f2tf(v1.w);
            d2[0]=f2tf(v2.x); d2[1]=f2tf(v2.y); d2[2]=f2tf(v2.z); d2[3]=f2tf(v2.w);
        }
        __syncthreads();
#pragma unroll
        for (int ks = 0; ks < 8; ks++) {
            unsigned a[4];
            const float* aw = sX + (16*wn)*SA;
            a[0] = ldsu(&aw[ lr    *SA + 8*ks + lc    ]);
            a[1] = ldsu(&aw[(lr+8) *SA + 8*ks + lc    ]);
            a[2] = ldsu(&aw[ lr    *SA + 8*ks + lc + 4]);
            a[3] = ldsu(&aw[(lr+8) *SA + 8*ks + lc + 4]);
#pragma unroll
            for (int j = 0; j < 8; j++) {
                unsigned b1[2], b2[2];
                b1[0] = ldsu(&sK[(8*ks + lc    )*SB + 64*wd + 8*j + lr]);
                b1[1] = ldsu(&sK[(8*ks + lc + 4)*SB + 64*wd + 8*j + lr]);
                b2[0] = ldsu(&sW[(8*ks + lc    )*SB + 64*wd + 8*j + lr]);
                b2[1] = ldsu(&sW[(8*ks + lc + 4)*SB + 64*wd + 8*j + lr]);
                mma_tf32(accK[j], a, b1);
                mma_tf32(accW[j], a, b2);
            }
        }
        __syncthreads();
    }
#pragma unroll
    for (int j = 0; j < 8; j++) {
        int rr = row0 + 16*wn + lr, cc = 64*wd + 8*j + 2*lc;
        int b0_ = rr >> 11, n0_ = rr & (Nv - 1);
        int b1_ = (rr+8) >> 11, n1_ = (rr+8) & (Nv - 1);
        *(float2*)&g_Xs[(size_t)rr    *Dv + cc] =
            make_float2(accW[j][0] + bskip[cc], accW[j][1] + bskip[cc+1]);
        *(float2*)&g_Xs[(size_t)(rr+8)*Dv + cc] =
            make_float2(accW[j][2] + bskip[cc], accW[j][3] + bskip[cc+1]);
        g_Hx0T[((size_t)b0_*Dv + cc  )*Nv + n0_] = __float2bfloat16(accK[j][0] + bias[cc]);
        g_Hx0T[((size_t)b0_*Dv + cc+1)*Nv + n0_] = __float2bfloat16(accK[j][1] + bias[cc+1]);
        g_Hx0T[((size_t)b1_*Dv + cc  )*Nv + n1_] = __float2bfloat16(accK[j][2] + bias[cc]);
        g_Hx0T[((size_t)b1_*Dv + cc+1)*Nv + n1_] = __float2bfloat16(accK[j][3] + bias[cc+1]);
    }
}

// ---------------------------------------------------------------------------
// K2: Hx = A @ Hx0  (bf16 mma + ldmatrix), double-buffered pipeline (R13).
// ---------------------------------------------------------------------------
__global__ __launch_bounds__(256, 1) void aggr_bf16_kernel(
    const float* __restrict__ A, float* __restrict__ outA)
{
    extern __shared__ unsigned smw[];
    const int tid = threadIdx.x, warp = tid >> 5, lane = tid & 31;
    const int lr = lane >> 2, lc = lane & 3;
    const int an = warp & 1, ad = (warp >> 1) & 1, ak = warp >> 2;
    const int b = blockIdx.y, n0 = blockIdx.x * 64;
    const float* Ab = A + (size_t)b * Nv * Nv;
    const unsigned* HtW0 = (const unsigned*)g_Hx0T + (size_t)b * Dv * (Nv/2);
    const int aoff = AOFF(36), boff = BOFF(36);
    const int rA = tid >> 5, wA = tid & 31;

    float2 aReg[8];
    auto load_a = [&](int k0) {
#pragma unroll
        for (int s = 0; s < 8; s++)
            aReg[s] = *(const float2*)&Ab[(size_t)(n0 + rA + 8*s)*Nv + k0 + 2*wA];
    };
    auto store_a = [&](unsigned* sA, int k0) {
#pragma unroll
        for (int s = 0; s < 8; s++) {
            sA[(rA + 8*s)*36 + wA] = pack_bf16(aReg[s].x, aReg[s].y);
            *(float2*)&outA[((size_t)b*Nv + n0 + rA + 8*s)*Nv + k0 + 2*wA] = aReg[s];
        }
    };
    auto issue_b = [&](unsigned* sB, int k0) {
#pragma unroll
        for (int s = 0; s < 4; s++) {
            int i4 = tid + 256*s; int d = i4 >> 3, c4 = (i4 & 7) << 2;
            cpa16(&sB[d*36 + c4], &HtW0[(size_t)d*(Nv/2) + (k0 >> 1) + c4]);
        }
    };

    float acc[2][8][4];
#pragma unroll
    for (int f = 0; f < 2; f++)
#pragma unroll
        for (int j = 0; j < 8; j++)
#pragma unroll
            for (int i = 0; i < 4; i++) acc[f][j][i] = 0.f;

    load_a(0);
    issue_b(smw + 64*36, 0);
    asm volatile("cp.async.commit_group;");

    for (int kt = 0; kt < Nv/64; kt++) {
        const int k0 = kt * 64;
        unsigned* cur = smw + (kt & 1) * AG_W;
        unsigned* sA = cur;
        unsigned* sB = cur + 64*36;

        store_a(sA, k0);
        if (kt + 1 < Nv/64) {
            issue_b(smw + ((kt + 1) & 1) * AG_W + 64*36, k0 + 64);
            asm volatile("cp.async.commit_group;");
            asm volatile("cp.async.wait_group 1;");
        } else {
            asm volatile("cp.async.wait_group 0;");
        }
        __syncthreads();

        if (kt + 1 < Nv/64) load_a(k0 + 64);

#pragma unroll
        for (int ks = 0; ks < 2; ks++) {
            int kw = ak*16 + ks*8;
            unsigned a0[4], a1[4], bb[4];
            ldsm4(a0, sA + (an*32     )*36 + aoff + kw);
            ldsm4(a1, sA + (an*32 + 16)*36 + aoff + kw);
#pragma unroll
            for (int p = 0; p < 4; p++) {
                ldsm4(bb, sB + (ad*64 + p*16)*36 + boff + kw);
                mma_bf16(acc[0][2*p    ], a0, bb    );
                mma_bf16(acc[0][2*p + 1], a0, bb + 2);
                mma_bf16(acc[1][2*p    ], a1, bb    );
                mma_bf16(acc[1][2*p + 1], a1, bb + 2);
            }
        }
        __syncthreads();
    }
    float* red = (float*)smw;
    if (ak == 1) {
        int base = (((warp - 4) * 32) + lane) * 64;
#pragma unroll
        for (int f = 0; f < 2; f++)
#pragma unroll
            for (int j = 0; j < 8; j++)
#pragma unroll
                for (int i = 0; i < 4; i++)
                    red[base + f*32 + j*4 + i] = acc[f][j][i];
    }
    __syncthreads();
    if (ak == 0) {
        int base = ((warp * 32) + lane) * 64;
        unsigned* Pb = (unsigned*)g_Hxb;
        __nv_bfloat16* Tb = g_HxT + (size_t)b * Dv * Nv;
#pragma unroll
        for (int f = 0; f < 2; f++)
#pragma unroll
            for (int j = 0; j < 8; j++) {
                float v0 = acc[f][j][0] + red[base + f*32 + j*4 + 0];
                float v1 = acc[f][j][1] + red[base + f*32 + j*4 + 1];
                float v2 = acc[f][j][2] + red[base + f*32 + j*4 + 2];
                float v3 = acc[f][j][3] + red[base + f*32 + j*4 + 3];
                int n  = an*32 + f*16 + lr;
                int cc = ad*64 + j*8 + 2*lc;
                Pb[(((size_t)b*Nv + n0+n  )*Dv + cc) >> 1] = pack_bf16(v0, v1);
                Pb[(((size_t)b*Nv + n0+n+8)*Dv + cc) >> 1] = pack_bf16(v2, v3);
                Tb[(size_t)(cc  )*Nv + n0+n  ] = __float2bfloat16(v0);
                Tb[(size_t)(cc+1)*Nv + n0+n  ] = __float2bfloat16(v1);
                Tb[(size_t)(cc  )*Nv + n0+n+8] = __float2bfloat16(v2);
                Tb[(size_t)(cc+1)*Nv + n0+n+8] = __float2bfloat16(v3);
            }
    }
}

// ---------------------------------------------------------------------------
// K4: fused attention (R13 proven core) + fused Q prologue.
// Prologue: Q_h[n0:64][128] = Hx[n0:64] @ attn[h] computed in-block into sQ
// (identical fragment math to the old q kernel -> bit-identical Q).
// Main loop: register-direct C, double-buffered cp.async tiles, 2 syncs/tile.
// ---------------------------------------------------------------------------
__global__ __launch_bounds__(256, 1) void attn_bf16_kernel(const float* __restrict__ A)
{
    extern __shared__ unsigned smw[];
    unsigned* sQ   = smw;                 // [4][64][WQ]
    unsigned* bufs = smw + SQ_W;          // 2 x TILE_W

    const int tid = threadIdx.x, warp = tid >> 5, lane = tid & 31;
    const int lr = lane >> 2, lc = lane & 3;
    const int g1n = warp & 1, g1m = warp >> 1;   // main-loop roles
    const int qn  = warp & 1, qd  = warp >> 1;   // prologue roles (q layout)
    const int b = blockIdx.y, n0 = blockIdx.x * 64;
    const float* Ab = A + (size_t)b * Nv * Nv;
    const unsigned* HbW = (const unsigned*)g_Hxb + (size_t)b * Nv * (Dv/2);
    const unsigned* HtW = (const unsigned*)g_HxT + (size_t)b * Dv * (Nv/2);
    const int aoffQ = AOFF(WQ), boffQ = BOFF(WQ), boffT = BOFF(WT);

    // ======== Q prologue: compute sQ in-block ========
    {
        unsigned* sHxq = bufs;            // 64 x WQ (buf0 low)
#pragma unroll
        for (int s = 0; s < 4; s++) {     // Hx tile: 64 x 64 words
            int i4 = tid + 256*s; int r = i4 >> 4, c4 = (i4 & 15) << 2;
            *(uint4*)&sHxq[r*WQ + c4] = *(const uint4*)&HbW[(size_t)(n0 + r)*(Dv/2) + c4];
        }
        for (int h = 0; h < Hv; h++) {
            // alternate attnT slots: buf1 base / buf0 high (slot(h+1)=slot(h-1),
            // whose readers finished before this iteration's barrier)
            unsigned* sAt = (h & 1) ? (bufs + 64*WQ) : (bufs + TILE_W);
            const unsigned* ATW = (const unsigned*)g_attnT + (size_t)h * Dv * (Dv/2);
#pragma unroll
            for (int s = 0; s < 8; s++) {  // attnT_h: 128 x 64 words
                int i4 = tid + 256*s; int e = i4 >> 4, c4 = (i4 & 15) << 2;
                *(uint4*)&sAt[e*WQ + c4] = *(const uint4*)&ATW[(size_t)e*(Dv/2) + c4];
            }
            __syncthreads();

            float qa[2][4][4];
#pragma unroll
            for (int f = 0; f < 2; f++)
#pragma unroll
                for (int j = 0; j < 4; j++)
#pragma unroll
                    for (int i = 0; i < 4; i++) qa[f][j][i] = 0.f;
#pragma unroll
            for (int ks = 0; ks < 8; ks++) {
                unsigned a0[4], a1[4], bb[4];
                ldsm4(a0, sHxq + (qn*32     )*WQ + aoffQ + 8*ks);
                ldsm4(a1, sHxq + (qn*32 + 16)*WQ + aoffQ + 8*ks);
#pragma unroll
                for (int p = 0; p < 2; p++) {
                    ldsm4(bb, sAt + (qd*32 + p*16)*WQ + boffQ + 8*ks);
                    mma_bf16(qa[0][2*p    ], a0, bb    );
                    mma_bf16(qa[0][2*p + 1], a0, bb + 2);
                    mma_bf16(qa[1][2*p    ], a1, bb    );
                    mma_bf16(qa[1][2*p + 1], a1, bb + 2);
                }
            }
#pragma unroll
            for (int f = 0; f < 2; f++)
#pragma unroll
                for (int j = 0; j < 4; j++) {
                    int n = qn*32 + f*16 + lr, cc = qd*32 + j*8 + 2*lc;
                    sQ[(h*64 + n    )*WQ + (cc >> 1)] = pack_bf16(qa[f][j][0], qa[f][j][1]);
                    sQ[(h*64 + n + 8)*WQ + (cc >> 1)] = pack_bf16(qa[f][j][2], qa[f][j][3]);
                }
        }
        __syncthreads();   // Q complete, buffers free for the tile pipeline
    }

    // ======== main loop (R13 proven) ========
    auto issue_tile = [&](unsigned* buf, int m0) {
        unsigned* dHx  = buf;
        unsigned* dHxT = buf + 64*WQ;
        float*    dAr  = (float*)(buf + 64*WQ + 128*WT);
#pragma unroll
        for (int s = 0; s < 4; s++) {
            int i4 = tid + 256*s; int r = i4 >> 4, c4 = (i4 & 15) << 2;
            cpa16(&dHx[r*WQ + c4], &HbW[(size_t)(m0 + r)*(Dv/2) + c4]);
        }
#pragma unroll
        for (int s = 0; s < 4; s++) {
            int i4 = tid + 256*s; int d = i4 >> 3, c4 = (i4 & 7) << 2;
            cpa16(&dHxT[d*WT + c4], &HtW[(size_t)d*(Nv/2) + (m0 >> 1) + c4]);
        }
#pragma unroll
        for (int s = 0; s < 4; s++) {
            int i4 = tid + 256*s; int r = i4 >> 4, c4 = (i4 & 15) << 2;
            cpa16((unsigned*)&dAr[r*68 + c4], &Ab[(size_t)(n0 + r)*Nv + m0 + c4]);
        }
    };

    issue_tile(bufs, 0);
    asm volatile("cp.async.commit_group;");

    float acc[2][16][4];
#pragma unroll
    for (int f = 0; f < 2; f++)
#pragma unroll
        for (int j = 0; j < 16; j++)
#pragma unroll
            for (int i = 0; i < 4; i++) acc[f][j][i] = 0.f;

    for (int mt = 0; mt < NT; mt++) {
        unsigned* cur = bufs + (mt & 1) * TILE_W;
        if (mt + 1 < NT) {
            issue_tile(bufs + ((mt + 1) & 1) * TILE_W, (mt + 1) * 64);
            asm volatile("cp.async.commit_group;");
            asm volatile("cp.async.wait_group 1;");
        } else {
            asm volatile("cp.async.wait_group 0;");
        }
        __syncthreads();

        const unsigned* bHx  = cur;
        const unsigned* bHxT = cur + 64*WQ;
        const float*    bAr  = (const float*)(cur + 64*WQ + 128*WT);

        float aA[2][2][4];
#pragma unroll
        for (int f = 0; f < 2; f++)
#pragma unroll
            for (int jm = 0; jm < 2; jm++) {
                int n  = g1n*32 + f*16 + lr;
                int mm = g1m*16 + jm*8 + 2*lc;
                float2 a01 = *(const float2*)&bAr[ n    *68 + mm];
                float2 a23 = *(const float2*)&bAr[(n+8) *68 + mm];
                aA[f][jm][0] = a01.x; aA[f][jm][1] = a01.y;
                aA[f][jm][2] = a23.x; aA[f][jm][3] = a23.y;
            }

        float C[2][2][4];
#pragma unroll
        for (int f = 0; f < 2; f++)
#pragma unroll
            for (int jm = 0; jm < 2; jm++)
#pragma unroll
                for (int i = 0; i < 4; i++) C[f][jm][i] = 0.f;

#pragma unroll
        for (int h = 0; h < Hv; h++) {
            float s4[2][2][4];
#pragma unroll
            for (int f = 0; f < 2; f++)
#pragma unroll
                for (int jm = 0; jm < 2; jm++)
#pragma unroll
                    for (int i = 0; i < 4; i++) s4[f][jm][i] = 0.f;
            const unsigned* q = sQ + (h*64 + g1n*32)*WQ;
#pragma unroll
            for (int ks = 0; ks < 8; ks++) {
                unsigned a0[4], a1[4], bb[4];
                ldsm4(a0, q +         aoffQ + 8*ks);
                ldsm4(a1, q + 16*WQ + aoffQ + 8*ks);
                ldsm4(bb, bHx + (g1m*16)*WQ + boffQ + 8*ks);
                mma_bf16(s4[0][0], a0, bb    );
                mma_bf16(s4[0][1], a0, bb + 2);
                mma_bf16(s4[1][0], a1, bb    );
                mma_bf16(s4[1][1], a1, bb + 2);
            }
#pragma unroll
            for (int f = 0; f < 2; f++)
#pragma unroll
                for (int jm = 0; jm < 2; jm++)
#pragma unroll
                    for (int i = 0; i < 4; i++)
                        C[f][jm][i] += tanh_fast(aA[f][jm][i] * s4[f][jm][i]);
        }

        unsigned aC[2][4];
#pragma unroll
        for (int f = 0; f < 2; f++) {
            aC[f][0] = pack_bf16(C[f][0][0], C[f][0][1]);
            aC[f][1] = pack_bf16(C[f][0][2], C[f][0][3]);
            aC[f][2] = pack_bf16(C[f][1][0], C[f][1][1]);
            aC[f][3] = pack_bf16(C[f][1][2], C[f][1][3]);
        }

#pragma unroll
        for (int p = 0; p < 8; p++) {
            unsigned bb[4];
            ldsm4(bb, bHxT + (p*16)*WT + boffT + g1m*8);
            mma_bf16(acc[0][2*p    ], aC[0], bb    );
            mma_bf16(acc[0][2*p + 1], aC[0], bb + 2);
            mma_bf16(acc[1][2*p    ], aC[1], bb    );
            mma_bf16(acc[1][2*p + 1], aC[1], bb + 2);
        }
        __syncthreads();
    }

    float* red = (float*)smw;
    if (g1m > 0) {
        int base = ((((g1m - 1)*2 + g1n) * 32) + lane) * 128;
#pragma unroll
        for (int f = 0; f < 2; f++)
#pragma unroll
            for (int j = 0; j < 16; j++)
#pragma unroll
                for (int i = 0; i < 4; i++)
                    red[base + f*64 + j*4 + i] = acc[f][j][i];
    }
    __syncthreads();
    if (g1m == 0) {
        float* Ho = g_Hout + ((size_t)b*Nv + n0)*Dv;
#pragma unroll
        for (int w = 0; w < 3; w++) {
            int base = (((w*2 + g1n) * 32) + lane) * 128;
#pragma unroll
            for (int f = 0; f < 2; f++)
#pragma unroll
                for (int j = 0; j < 16; j++)
#pragma unroll
                    for (int i = 0; i < 4; i++)
                        acc[f][j][i] += red[base + f*64 + j*4 + i];
        }
#pragma unroll
        for (int f = 0; f < 2; f++)
#pragma unroll
            for (int j = 0; j < 16; j++) {
                int n = g1n*32 + f*16 + lr;
                int d = (j >> 1)*16 + (j & 1)*8 + 2*lc;
                float v0 = fmaxf(acc[f][j][0] * 0.25f, 0.f);
                float v1 = fmaxf(acc[f][j][1] * 0.25f, 0.f);
                float v2 = fmaxf(acc[f][j][2] * 0.25f, 0.f);
                float v3 = fmaxf(acc[f][j][3] * 0.25f, 0.f);
                *(float2*)&Ho[(size_t)n    *Dv + d] = make_float2(v0, v1);
                *(float2*)&Ho[(size_t)(n+8)*Dv + d] = make_float2(v2, v3);
            }
    }
}

// ---------------------------------------------------------------------------
// K5: gate (bf16 mma, K=256 fused): z = sigmoid([Hout|Xs]@[WuT;WxT] + biases)
//     out = Hout*z + Xs*(1-z)   (blend in f32)
// ---------------------------------------------------------------------------
__global__ __launch_bounds__(256, 1) void gate_mma_kernel(
    const float* __restrict__ bu, const float* __restrict__ bx,
    const float* __restrict__ ub, float* __restrict__ out)
{
    extern __shared__ unsigned smw[];
    float*    sHo = (float*)smw;            // [64][132] f32
    float*    sXs = sHo + 64*132;           // [64][132] f32
    unsigned* sAg = smw + 2*64*132;         // [64][WG]
    unsigned* sBg = sAg + 64*WG;            // [128][WG]
    const int tid = threadIdx.x, warp = tid >> 5, lane = tid & 31;
    const int lr = lane >> 2, lc = lane & 3;
    const int gn = warp & 1, gc = warp >> 1;
    const int row0 = blockIdx.x * 64;
    const int aoff = AOFF(WG), boff = BOFF(WG);

#pragma unroll
    for (int s = 0; s < 8; s++) {
        int i4 = tid + 256*s; int r = i4 >> 5, c4 = (i4 & 31) * 4;
        float4 vh = *(const float4*)&g_Hout[(size_t)(row0 + r)*Dv + c4];
        float4 vx = *(const float4*)&g_Xs [(size_t)(row0 + r)*Dv + c4];
        *(float4*)&sHo[r*132 + c4] = vh;
        *(float4*)&sXs[r*132 + c4] = vx;
        sAg[r*WG + (c4 >> 1)    ]      = pack_bf16(vh.x, vh.y);
        sAg[r*WG + (c4 >> 1) + 1]      = pack_bf16(vh.z, vh.w);
        sAg[r*WG + 64 + (c4 >> 1)    ] = pack_bf16(vx.x, vx.y);
        sAg[r*WG + 64 + (c4 >> 1) + 1] = pack_bf16(vx.z, vx.w);
    }
#pragma unroll
    for (int s = 0; s < 8; s++) {
        int i4 = tid + 256*s; int c = i4 >> 4, w4 = (i4 & 15) << 2;
        *(uint4*)&sBg[c*WG + w4]      = *(const uint4*)&((const unsigned*)g_WuT)[(size_t)c*64 + w4];
        *(uint4*)&sBg[c*WG + 64 + w4] = *(const uint4*)&((const unsigned*)g_WxT)[(size_t)c*64 + w4];
    }
    __syncthreads();

    float acc[2][4][4];
#pragma unroll
    for (int f = 0; f < 2; f++)
#pragma unroll
        for (int j = 0; j < 4; j++)
#pragma unroll
            for (int i = 0; i < 4; i++) acc[f][j][i] = 0.f;

#pragma unroll
    for (int ks = 0; ks < 16; ks++) {      // K = 256
        unsigned a0[4], a1[4], bb[4];
        ldsm4(a0, sAg + (gn*32     )*WG + aoff + 8*ks);
        ldsm4(a1, sAg + (gn*32 + 16)*WG + aoff + 8*ks);
#pragma unroll
        for (int p = 0; p < 2; p++) {
            ldsm4(bb, sBg + (gc*32 + p*16)*WG + boff + 8*ks);
            mma_bf16(acc[0][2*p    ], a0, bb    );
            mma_bf16(acc[0][2*p + 1], a0, bb + 2);
            mma_bf16(acc[1][2*p    ], a1, bb    );
            mma_bf16(acc[1][2*p + 1], a1, bb + 2);
        }
    }

#pragma unroll
    for (int f = 0; f < 2; f++)
#pragma unroll
        for (int j = 0; j < 4; j++) {
            int n = gn*32 + f*16 + lr, cc = gc*32 + j*8 + 2*lc;
            float bs0 = bu[cc]   + bx[cc]   + ub[cc];
            float bs1 = bu[cc+1] + bx[cc+1] + ub[cc+1];
            float2 h0 = *(const float2*)&sHo[ n    *132 + cc];
            float2 h1 = *(const float2*)&sHo[(n+8) *132 + cc];
            float2 x0 = *(const float2*)&sXs[ n    *132 + cc];
            float2 x1 = *(const float2*)&sXs[(n+8) *132 + cc];
            float z0 = 1.f / (1.f + expf(-(acc[f][j][0] + bs0)));
            float z1 = 1.f / (1.f + expf(-(acc[f][j][1] + bs1)));
            float z2 = 1.f / (1.f + expf(-(acc[f][j][2] + bs0)));
            float z3 = 1.f / (1.f + expf(-(acc[f][j][3] + bs1)));
            *(float2*)&out[(size_t)(row0 + n    )*Dv + cc] =
                make_float2(h0.x*z0 + x0.x*(1.f - z0), h0.y*z1 + x0.y*(1.f - z1));
            *(float2*)&out[(size_t)(row0 + n + 8)*Dv + cc] =
                make_float2(h1.x*z2 + x1.x*(1.f - z2), h1.y*z3 + x1.y*(1.f - z3));
        }
}

// ---------------------------------------------------------------------------
extern "C" void kernel_launch(void* const* d_in, const int* in_sizes, int n_in,
                              void* d_out, int out_size)
{
    const float* X      = (const float*)d_in[0];
    const float* A      = (const float*)d_in[1];
    const float* Wk     = (const float*)d_in[2];
    const float* bias   = (const float*)d_in[3];
    const float* ub     = (const float*)d_in[4];
    const float* attn   = (const float*)d_in[5];
    const float* Wskip  = (const float*)d_in[6];
    const float* bskip  = (const float*)d_in[7];
    const float* Wu     = (const float*)d_in[8];
    const float* bu     = (const float*)d_in[9];
    const float* Wx     = (const float*)d_in[10];
    const float* bx     = (const float*)d_in[11];
    float* out = (float*)d_out;

    const int SM1 = (64*SA + 2*64*SB) * 4;
    const int SM2 = (2*AG_W) * 4;
    const int SM4 = (SQ_W + 2*TILE_W) * 4;          // 176,128 B
    const int SM5 = (2*64*132 + 64*WG + 128*WG) * 4;
    cudaFuncSetAttribute(proj_mma_kernel,  cudaFuncAttributeMaxDynamicSharedMemorySize, SM1);
    cudaFuncSetAttribute(aggr_bf16_kernel, cudaFuncAttributeMaxDynamicSharedMemorySize, SM2);
    cudaFuncSetAttribute(attn_bf16_kernel, cudaFuncAttributeMaxDynamicSharedMemorySize, SM4);
    cudaFuncSetAttribute(gate_mma_kernel,  cudaFuncAttributeMaxDynamicSharedMemorySize, SM5);

    prep_kernel     <<<192, 256>>>(attn, Wu, Wx);
    proj_mma_kernel <<<(Bv*Nv)/64, 256, SM1>>>(X, Wk, bias, Wskip, bskip);
    aggr_bf16_kernel<<<dim3(Nv/64, Bv), 256, SM2>>>(A, out + (size_t)Bv*Nv*Dv);
    attn_bf16_kernel<<<dim3(Nv/64, Bv), 256, SM4>>>(A);
    gate_mma_kernel <<<(Bv*Nv)/64, 256, SM5>>>(bu, bx, ub, out);
}